// round 15
// baseline (speedup 1.0000x reference)
#include <cuda_runtime.h>
#include <cuda_fp16.h>
#include <cstdint>

typedef unsigned int uint;

#define NT 256

// ---- global scratch + per-window-half completion flags ----
__device__ static float4 g_rel[1024 * 128 * 16];   // 32 MB, L2-resident
__device__ static int    g_flag[2048];             // zero-init; each launch restores zeros

__device__ __forceinline__ uint packh2(float lo, float hi) {
    __half2 h = __floats2half2_rn(lo, hi);
    return *(uint*)&h;
}
__device__ __forceinline__ void mma16(float c[4], const uint a[4], uint b0, uint b1) {
    asm volatile(
        "mma.sync.aligned.m16n8k16.row.col.f32.f16.f16.f32 "
        "{%0,%1,%2,%3}, {%4,%5,%6,%7}, {%8,%9}, {%0,%1,%2,%3};"
        : "+f"(c[0]), "+f"(c[1]), "+f"(c[2]), "+f"(c[3])
        : "r"(a[0]), "r"(a[1]), "r"(a[2]), "r"(a[3]), "r"(b0), "r"(b1));
}
__device__ __forceinline__ uint fmono(float x) {
    uint b = __float_as_uint(x);
    return b ^ (uint)((((int)b) >> 31) | 0x80000000);
}
__device__ __forceinline__ void cas(uint& a, uint& b) {
    uint lo = umin(a, b), hi = umax(a, b);
    a = lo; b = hi;
}
__device__ __forceinline__ void sort8(uint k[8]) {
    cas(k[0],k[1]); cas(k[2],k[3]); cas(k[4],k[5]); cas(k[6],k[7]);
    cas(k[0],k[2]); cas(k[1],k[3]); cas(k[4],k[6]); cas(k[5],k[7]);
    cas(k[1],k[2]); cas(k[5],k[6]); cas(k[0],k[4]); cas(k[1],k[5]);
    cas(k[2],k[6]); cas(k[3],k[7]);
    cas(k[1],k[4]); cas(k[3],k[6]);
    cas(k[2],k[4]); cas(k[3],k[5]);
    cas(k[3],k[4]);
}
__device__ __forceinline__ void pop_shift(uint k[8], uint kmin) {
    if (k[0] == kmin) {
        k[0]=k[1]; k[1]=k[2]; k[2]=k[3]; k[3]=k[4];
        k[4]=k[5]; k[5]=k[6]; k[6]=k[7]; k[7]=0xFFFFFFFFu;
    }
}
__device__ __forceinline__ void flag_release(int* p) {
    asm volatile("st.global.release.gpu.u32 [%0], %1;" :: "l"(p), "r"(1) : "memory");
}
__device__ __forceinline__ uint flag_acquire(const int* p) {
    uint v;
    asm volatile("ld.global.acquire.gpu.u32 %0, [%1];" : "=r"(v) : "l"(p) : "memory");
    return v;
}

// ---------------- dynamic smem layout (GEMM path; kNN uses prefix) ----------------
#define OFF_W1   0
#define OFF_B1   384
#define OFF_B2   512
#define OFF_B3   768
#define OFF_W2H  1280     // uint2[8][2][32]  = 4096
#define OFF_W3H  5376     // uint2[16][4][32] = 16384
#define OFF_SREL 21760    // float4[128*16]   = 32768
#define SMEM_TOTAL 54528

__global__ void __launch_bounds__(NT, 3)
mini_embedding_uni(const float* __restrict__ windows,
                   const float* __restrict__ W1, const float* __restrict__ b1,
                   const float* __restrict__ W2, const float* __restrict__ b2,
                   const float* __restrict__ W3, const float* __restrict__ b3,
                   float* __restrict__ out, int M)
{
    extern __shared__ unsigned char smraw[];

    const int tid  = threadIdx.x;
    const int w    = tid >> 5;
    const int lane = tid & 31;

    // bid layout: 3m -> kNN half0(m), 3m+1 -> kNN half1(m), 3m+2 -> GEMM(m)
    const int mwin = blockIdx.x / 3;
    const int role = blockIdx.x - 3 * mwin;

    if (role < 2) {
        // ===================== kNN path =====================
        float* px  = (float*)(smraw + 0);
        float* py  = (float*)(smraw + 512);
        float* pz  = (float*)(smraw + 1024);
        float* sqn = (float*)(smraw + 1536);

        const int m  = mwin;
        const int hw = role;

        const float* wptr = windows + (size_t)m * 128 * 3;
        for (int i = tid; i < 128; i += NT) {
            float x = wptr[i*3+0], y = wptr[i*3+1], z = wptr[i*3+2];
            px[i] = x; py[i] = y; pz[i] = z;
            sqn[i] = x*x + y*y + z*z;
        }
        __syncthreads();

        const int half = lane >> 4;
        const int n16  = lane & 15;
        const int jb   = n16 * 8;
        const int myrk = n16 >> 1;
        const bool hi2 = n16 & 1;

        #pragma unroll 1
        for (int i2 = 0; i2 < 2; ++i2) {
            const int q0 = hw*64 + w*8 + i2*4 + 2*half;
            const int q1 = q0 + 1;
            const float qx0 = px[q0], qy0 = py[q0], qz0 = pz[q0], sq0 = sqn[q0];
            const float qx1 = px[q1], qy1 = py[q1], qz1 = pz[q1], sq1 = sqn[q1];
            uint k0[8], k1[8];
            #pragma unroll
            for (int ii = 0; ii < 8; ++ii) {
                const int j = jb + ii;
                const float xj = px[j], yj = py[j], zj = pz[j], sj = sqn[j];
                float d0 = sq0 + sj - 2.0f*(qx0*xj + qy0*yj + qz0*zj);
                float d1 = sq1 + sj - 2.0f*(qx1*xj + qy1*yj + qz1*zj);
                k0[ii] = (fmono(d0) & 0xFFFFFF80u) | (uint)j;
                k1[ii] = (fmono(d1) & 0xFFFFFF80u) | (uint)j;
            }
            sort8(k0); sort8(k1);
            int idx0 = 0, idx1 = 0;
            #pragma unroll
            for (int r = 0; r < 8; ++r) {
                uint a0 = k0[0], b0v = k0[1];
                uint a1 = k1[0], b1v = k1[1];
                #pragma unroll
                for (int st = 1; st < 16; st <<= 1) {
                    uint oa0 = __shfl_xor_sync(0xffffffffu, a0, st, 16);
                    uint ob0 = __shfl_xor_sync(0xffffffffu, b0v, st, 16);
                    uint oa1 = __shfl_xor_sync(0xffffffffu, a1, st, 16);
                    uint ob1 = __shfl_xor_sync(0xffffffffu, b1v, st, 16);
                    uint n0 = umin(a0, oa0);
                    b0v = umin(umax(a0, oa0), umin(b0v, ob0));
                    a0 = n0;
                    uint n1 = umin(a1, oa1);
                    b1v = umin(umax(a1, oa1), umin(b1v, ob1));
                    a1 = n1;
                }
                if (r == myrk) {
                    idx0 = (int)((hi2 ? b0v : a0) & 127u);
                    idx1 = (int)((hi2 ? b1v : a1) & 127u);
                }
                pop_shift(k0, a0); pop_shift(k0, b0v);
                pop_shift(k1, a1); pop_shift(k1, b1v);
            }
            float rx0 = px[idx0] - qx0, ry0 = py[idx0] - qy0, rz0 = pz[idx0] - qz0;
            float rx1 = px[idx1] - qx1, ry1 = py[idx1] - qy1, rz1 = pz[idx1] - qz1;
            float mx0 = rx0*rx0 + ry0*ry0 + rz0*rz0;
            float mx1 = rx1*rx1 + ry1*ry1 + rz1*rz1;
            #pragma unroll
            for (int st = 1; st < 16; st <<= 1) {
                mx0 = fmaxf(mx0, __shfl_xor_sync(0xffffffffu, mx0, st, 16));
                mx1 = fmaxf(mx1, __shfl_xor_sync(0xffffffffu, mx1, st, 16));
            }
            float inv0 = 1.0f / fmaxf(sqrtf(mx0), 1e-8f);
            float inv1 = 1.0f / fmaxf(sqrtf(mx1), 1e-8f);
            g_rel[((size_t)m*128 + q0)*16 + n16] = make_float4(rx0*inv0, ry0*inv0, rz0*inv0, 0.0f);
            g_rel[((size_t)m*128 + q1)*16 + n16] = make_float4(rx1*inv1, ry1*inv1, rz1*inv1, 0.0f);
        }
        __syncthreads();
        if (tid == 0) flag_release(&g_flag[2*m + hw]);
        return;
    }

    // ===================== GEMM path =====================
    float* sW1 = (float*)(smraw + OFF_W1);
    float* sb1 = (float*)(smraw + OFF_B1);
    float* sb2 = (float*)(smraw + OFF_B2);
    float* sb3 = (float*)(smraw + OFF_B3);
    uint2* w2H = (uint2*)(smraw + OFF_W2H);
    uint2* w3H = (uint2*)(smraw + OFF_W3H);
    float4* srel = (float4*)(smraw + OFF_SREL);

    const int g    = lane >> 2;
    const int tg   = lane & 3;
    const int m    = mwin;

    const bool g0 = (lane >> 2) & 1;
    const bool g1 = (lane >> 3) & 1;
    const int  g2 = (lane >> 4) & 1;

    // ---- weight prologue (independent of kNN results) ----
    for (int i = tid; i < 96;  i += NT) sW1[i] = W1[i];
    for (int i = tid; i < 32;  i += NT) sb1[i] = b1[i];
    for (int i = tid; i < 64;  i += NT) sb2[i] = b2[i];
    for (int i = tid; i < 128; i += NT) sb3[i] = b3[i];
    for (int i = tid; i < 512; i += NT) {
        int ln = i & 31, kt = (i >> 5) & 1, nt = i >> 6;
        int gg = ln >> 2, tt = ln & 3;
        int c = nt*8 + gg;
        int k0 = 16*kt + 2*tt;
        w2H[i] = make_uint2(packh2(W2[k0*64 + c],     W2[(k0+1)*64 + c]),
                            packh2(W2[(k0+8)*64 + c], W2[(k0+9)*64 + c]));
    }
    for (int i = tid; i < 2048; i += NT) {
        int ln = i & 31, kt = (i >> 5) & 3, ntg = i >> 7;
        int gg = ln >> 2, tt = ln & 3;
        int c = ntg*8 + gg;
        int k0 = 16*kt + 2*tt;
        w3H[i] = make_uint2(packh2(W3[k0*128 + c],     W3[(k0+1)*128 + c]),
                            packh2(W3[(k0+8)*128 + c], W3[(k0+9)*128 + c]));
    }

    // ---- wait for this window's kNN halves, then reset flags (sole consumer) ----
    if (tid == 0) {
        while (flag_acquire(&g_flag[2*m])     == 0) __nanosleep(64);
        while (flag_acquire(&g_flag[2*m + 1]) == 0) __nanosleep(64);
        g_flag[2*m] = 0;
        g_flag[2*m + 1] = 0;
    }
    __syncthreads();

    {
        const float4* src = &g_rel[(size_t)m * 2048];
        for (int i = tid; i < 2048; i += NT) srel[i] = src[i];
    }
    __syncthreads();

    const uint2* w2p = w2H + lane;
    const uint2* w3p = w3H + lane;

    // ---- per-chunk GEMM pipeline: 8 chunks of (2 points x 16 neighbors) ----
    #pragma unroll 1
    for (int ch = 0; ch < 8; ++ch) {
        const int pA = 16*w + 2*ch;
        const int pB = pA + 1;

        uint af[2][4][4];

        #pragma unroll
        for (int mm = 0; mm < 2; ++mm) {
            const int p = mm ? pB : pA;
            float4 v0 = srel[p*16 + g];
            float4 v8 = srel[p*16 + g + 8];

            uint afr[2][4];
            #pragma unroll
            for (int blk = 0; blk < 4; ++blk) {
                const int c0 = blk*8 + 2*tg;
                const float wa0 = sW1[c0],   wb0 = sW1[32+c0],   wc0 = sW1[64+c0],   bb0 = sb1[c0];
                const float wa1 = sW1[c0+1], wb1 = sW1[32+c0+1], wc1 = sW1[64+c0+1], bb1 = sb1[c0+1];
                const int kt = blk >> 1, hi = blk & 1;
                float hg0  = fmaxf(bb0 + v0.x*wa0 + v0.y*wb0 + v0.z*wc0, 0.0f);
                float hg1  = fmaxf(bb1 + v0.x*wa1 + v0.y*wb1 + v0.z*wc1, 0.0f);
                float hg80 = fmaxf(bb0 + v8.x*wa0 + v8.y*wb0 + v8.z*wc0, 0.0f);
                float hg81 = fmaxf(bb1 + v8.x*wa1 + v8.y*wb1 + v8.z*wc1, 0.0f);
                afr[kt][hi*2+0] = packh2(hg0,  hg1);
                afr[kt][hi*2+1] = packh2(hg80, hg81);
            }

            float c2[8][4];
            #pragma unroll
            for (int nt = 0; nt < 8; ++nt)
                #pragma unroll
                for (int r = 0; r < 4; ++r) c2[nt][r] = 0.0f;
            #pragma unroll
            for (int kt = 0; kt < 2; ++kt) {
                #pragma unroll
                for (int nt = 0; nt < 8; ++nt) {
                    uint2 bq = w2p[(nt*2 + kt)*32];
                    mma16(c2[nt], afr[kt], bq.x, bq.y);
                }
            }

            #pragma unroll
            for (int kt = 0; kt < 4; ++kt) {
                const int colA = (2*kt)*8 + 2*tg;
                const int colB = (2*kt+1)*8 + 2*tg;
                const float bA0 = sb2[colA], bA1 = sb2[colA+1];
                const float bB0 = sb2[colB], bB1 = sb2[colB+1];
                af[mm][kt][0] = packh2(fmaxf(c2[2*kt][0]   + bA0, 0.0f),
                                       fmaxf(c2[2*kt][1]   + bA1, 0.0f));
                af[mm][kt][1] = packh2(fmaxf(c2[2*kt][2]   + bA0, 0.0f),
                                       fmaxf(c2[2*kt][3]   + bA1, 0.0f));
                af[mm][kt][2] = packh2(fmaxf(c2[2*kt+1][0] + bB0, 0.0f),
                                       fmaxf(c2[2*kt+1][1] + bB1, 0.0f));
                af[mm][kt][3] = packh2(fmaxf(c2[2*kt+1][2] + bB0, 0.0f),
                                       fmaxf(c2[2*kt+1][3] + bB1, 0.0f));
            }
        }

        const size_t rbA = ((size_t)(m*128 + pA)) * 128;
        const size_t rbB = ((size_t)(m*128 + pB)) * 128;
        #pragma unroll 1
        for (int pp = 0; pp < 2; ++pp) {
            #pragma unroll 1
            for (int nh = 0; nh < 2; ++nh) {
                float c3[2][4][4];
                #pragma unroll
                for (int n2 = 0; n2 < 4; ++n2)
                    #pragma unroll
                    for (int r = 0; r < 4; ++r) { c3[0][n2][r] = 0.0f; c3[1][n2][r] = 0.0f; }
                #pragma unroll
                for (int kt = 0; kt < 4; ++kt) {
                    #pragma unroll
                    for (int n2 = 0; n2 < 4; ++n2) {
                        const int ntg = pp*8 + nh*4 + n2;
                        uint2 bq = w3p[(ntg*4 + kt)*32];
                        mma16(c3[0][n2], af[0][kt], bq.x, bq.y);
                        mma16(c3[1][n2], af[1][kt], bq.x, bq.y);
                    }
                }
                #pragma unroll
                for (int mm = 0; mm < 2; ++mm) {
                    float P[4][2];
                    #pragma unroll
                    for (int n2 = 0; n2 < 4; ++n2) {
                        P[n2][0] = fmaxf(c3[mm][n2][0], c3[mm][n2][2]);
                        P[n2][1] = fmaxf(c3[mm][n2][1], c3[mm][n2][3]);
                    }
                    float e0 = g0 ? P[0][0] : P[1][0];
                    float e1 = g0 ? P[0][1] : P[1][1];
                    float e2 = g0 ? P[2][0] : P[3][0];
                    float e3 = g0 ? P[2][1] : P[3][1];
                    float K0v0 = g0 ? P[1][0] : P[0][0];
                    float K0v1 = g0 ? P[1][1] : P[0][1];
                    float K1v0 = g0 ? P[3][0] : P[2][0];
                    float K1v1 = g0 ? P[3][1] : P[2][1];
                    K0v0 = fmaxf(K0v0, __shfl_xor_sync(0xffffffffu, e0, 4));
                    K0v1 = fmaxf(K0v1, __shfl_xor_sync(0xffffffffu, e1, 4));
                    K1v0 = fmaxf(K1v0, __shfl_xor_sync(0xffffffffu, e2, 4));
                    K1v1 = fmaxf(K1v1, __shfl_xor_sync(0xffffffffu, e3, 4));
                    float f0  = g1 ? K0v0 : K1v0;
                    float f1  = g1 ? K0v1 : K1v1;
                    float Rv0 = g1 ? K1v0 : K0v0;
                    float Rv1 = g1 ? K1v1 : K0v1;
                    Rv0 = fmaxf(Rv0, __shfl_xor_sync(0xffffffffu, f0, 8));
                    Rv1 = fmaxf(Rv1, __shfl_xor_sync(0xffffffffu, f1, 8));
                    Rv0 = fmaxf(Rv0, __shfl_xor_sync(0xffffffffu, Rv0, 16));
                    Rv1 = fmaxf(Rv1, __shfl_xor_sync(0xffffffffu, Rv1, 16));
                    if (g2 == nh) {
                        const int col = (pp*8 + nh*4 + (g & 3))*8 + 2*tg;
                        float2 b3v = *(float2*)&sb3[col];
                        *(float2*)&out[(mm ? rbB : rbA) + col] =
                            make_float2(Rv0 + b3v.x, Rv1 + b3v.y);
                    }
                }
            }
        }
    }
}

extern "C" void kernel_launch(void* const* d_in, const int* in_sizes, int n_in,
                              void* d_out, int out_size)
{
    const float* windows = (const float*)d_in[0];
    const float* W1 = (const float*)d_in[1];
    const float* b1 = (const float*)d_in[2];
    const float* W2 = (const float*)d_in[3];
    const float* b2 = (const float*)d_in[4];
    const float* W3 = (const float*)d_in[5];
    const float* b3 = (const float*)d_in[6];
    float* out = (float*)d_out;

    cudaFuncSetAttribute(mini_embedding_uni,
                         cudaFuncAttributeMaxDynamicSharedMemorySize, SMEM_TOTAL);

    const int M = in_sizes[0] / (128 * 3);
    mini_embedding_uni<<<3 * M, NT, SMEM_TOTAL>>>(windows, W1, b1, W2, b2, W3, b3, out, M);
}

// round 16
// speedup vs baseline: 1.2217x; 1.2217x over previous
#include <cuda_runtime.h>
#include <cuda_fp16.h>
#include <cstdint>

typedef unsigned int uint;

#define NT 256

// ---------------- dynamic smem layout (bytes) ----------------
#define OFF_W1   0        // 3*32*4 = 384
#define OFF_B1   384
#define OFF_B2   512
#define OFF_B3   768
#define OFF_PX   1280     // 4*512 = 2048 (points + sq norms)
#define OFF_W2H  3328     // uint2[8][2][32]  = 4096
#define OFF_W3H  7424     // uint2[16][4][32] = 16384
#define OFF_SREL 23808    // float4[128*16]   = 32768
#define SMEM_TOTAL 56576

__device__ __forceinline__ uint packh2(float lo, float hi) {
    __half2 h = __floats2half2_rn(lo, hi);
    return *(uint*)&h;
}
__device__ __forceinline__ void mma16(float c[4], const uint a[4], uint b0, uint b1) {
    asm volatile(
        "mma.sync.aligned.m16n8k16.row.col.f32.f16.f16.f32 "
        "{%0,%1,%2,%3}, {%4,%5,%6,%7}, {%8,%9}, {%0,%1,%2,%3};"
        : "+f"(c[0]), "+f"(c[1]), "+f"(c[2]), "+f"(c[3])
        : "r"(a[0]), "r"(a[1]), "r"(a[2]), "r"(a[3]), "r"(b0), "r"(b1));
}
__device__ __forceinline__ uint fmono(float x) {
    uint b = __float_as_uint(x);
    return b ^ (uint)((((int)b) >> 31) | 0x80000000);
}
__device__ __forceinline__ void cas(uint& a, uint& b) {
    uint lo = umin(a, b), hi = umax(a, b);
    a = lo; b = hi;
}
__device__ __forceinline__ void sort8(uint k[8]) {
    cas(k[0],k[1]); cas(k[2],k[3]); cas(k[4],k[5]); cas(k[6],k[7]);
    cas(k[0],k[2]); cas(k[1],k[3]); cas(k[4],k[6]); cas(k[5],k[7]);
    cas(k[1],k[2]); cas(k[5],k[6]); cas(k[0],k[4]); cas(k[1],k[5]);
    cas(k[2],k[6]); cas(k[3],k[7]);
    cas(k[1],k[4]); cas(k[3],k[6]);
    cas(k[2],k[4]); cas(k[3],k[5]);
    cas(k[3],k[4]);
}
__device__ __forceinline__ void pop_shift(uint k[8], uint kmin) {
    if (k[0] == kmin) {
        k[0]=k[1]; k[1]=k[2]; k[2]=k[3]; k[3]=k[4];
        k[4]=k[5]; k[5]=k[6]; k[6]=k[7]; k[7]=0xFFFFFFFFu;
    }
}

__global__ void __launch_bounds__(NT, 3)
mini_embedding_fused(const float* __restrict__ windows,
                     const float* __restrict__ W1, const float* __restrict__ b1,
                     const float* __restrict__ W2, const float* __restrict__ b2,
                     const float* __restrict__ W3, const float* __restrict__ b3,
                     float* __restrict__ out)
{
    extern __shared__ unsigned char smraw[];
    float* sW1 = (float*)(smraw + OFF_W1);
    float* sb1 = (float*)(smraw + OFF_B1);
    float* sb2 = (float*)(smraw + OFF_B2);
    float* sb3 = (float*)(smraw + OFF_B3);
    float* px  = (float*)(smraw + OFF_PX);
    float* py  = px + 128;
    float* pz  = px + 256;
    float* sqn = px + 384;
    uint2* w2H = (uint2*)(smraw + OFF_W2H);
    uint2* w3H = (uint2*)(smraw + OFF_W3H);
    float4* srel = (float4*)(smraw + OFF_SREL);

    const int tid  = threadIdx.x;
    const int w    = tid >> 5;
    const int lane = tid & 31;
    const int g    = lane >> 2;
    const int tg   = lane & 3;
    const int m    = blockIdx.x;

    const bool g0 = (lane >> 2) & 1;
    const bool g1 = (lane >> 3) & 1;
    const int  g2 = (lane >> 4) & 1;

    // ---- cooperative prep: points + weights ----
    const float* wptr = windows + (size_t)m * 128 * 3;
    for (int i = tid; i < 128; i += NT) {
        float x = wptr[i*3+0], y = wptr[i*3+1], z = wptr[i*3+2];
        px[i] = x; py[i] = y; pz[i] = z;
        sqn[i] = x*x + y*y + z*z;
    }
    for (int i = tid; i < 96;  i += NT) sW1[i] = W1[i];
    for (int i = tid; i < 32;  i += NT) sb1[i] = b1[i];
    for (int i = tid; i < 64;  i += NT) sb2[i] = b2[i];
    for (int i = tid; i < 128; i += NT) sb3[i] = b3[i];
    for (int i = tid; i < 512; i += NT) {
        int ln = i & 31, kt = (i >> 5) & 1, nt = i >> 6;
        int gg = ln >> 2, tt = ln & 3;
        int c = nt*8 + gg;
        int k0 = 16*kt + 2*tt;
        w2H[i] = make_uint2(packh2(W2[k0*64 + c],     W2[(k0+1)*64 + c]),
                            packh2(W2[(k0+8)*64 + c], W2[(k0+9)*64 + c]));
    }
    for (int i = tid; i < 2048; i += NT) {
        int ln = i & 31, kt = (i >> 5) & 3, ntg = i >> 7;
        int gg = ln >> 2, tt = ln & 3;
        int c = ntg*8 + gg;
        int k0 = 16*kt + 2*tt;
        w3H[i] = make_uint2(packh2(W3[k0*128 + c],     W3[(k0+1)*128 + c]),
                            packh2(W3[(k0+8)*128 + c], W3[(k0+9)*128 + c]));
    }
    __syncthreads();

    // ---- warp-local kNN + normalize: 16 points per warp, 2-rank rounds ----
    {
        const int half = lane >> 4;
        const int n16  = lane & 15;
        const int jb   = n16 * 8;
        const int myrk = n16 >> 1;
        const bool hi2 = n16 & 1;

        #pragma unroll 1
        for (int i4 = 0; i4 < 4; ++i4) {
            const int q0 = 16*w + 4*i4 + 2*half;
            const int q1 = q0 + 1;
            const float qx0 = px[q0], qy0 = py[q0], qz0 = pz[q0], sq0 = sqn[q0];
            const float qx1 = px[q1], qy1 = py[q1], qz1 = pz[q1], sq1 = sqn[q1];
            uint k0[8], k1[8];
            #pragma unroll
            for (int ii = 0; ii < 8; ++ii) {
                const int j = jb + ii;
                const float xj = px[j], yj = py[j], zj = pz[j], sj = sqn[j];
                float d0 = sq0 + sj - 2.0f*(qx0*xj + qy0*yj + qz0*zj);
                float d1 = sq1 + sj - 2.0f*(qx1*xj + qy1*yj + qz1*zj);
                k0[ii] = (fmono(d0) & 0xFFFFFF80u) | (uint)j;
                k1[ii] = (fmono(d1) & 0xFFFFFF80u) | (uint)j;
            }
            sort8(k0); sort8(k1);
            int idx0 = 0, idx1 = 0;
            #pragma unroll
            for (int r = 0; r < 8; ++r) {
                uint a0 = k0[0], b0v = k0[1];
                uint a1 = k1[0], b1v = k1[1];
                #pragma unroll
                for (int st = 1; st < 16; st <<= 1) {
                    uint oa0 = __shfl_xor_sync(0xffffffffu, a0, st, 16);
                    uint ob0 = __shfl_xor_sync(0xffffffffu, b0v, st, 16);
                    uint oa1 = __shfl_xor_sync(0xffffffffu, a1, st, 16);
                    uint ob1 = __shfl_xor_sync(0xffffffffu, b1v, st, 16);
                    uint n0 = umin(a0, oa0);
                    b0v = umin(umax(a0, oa0), umin(b0v, ob0));
                    a0 = n0;
                    uint n1 = umin(a1, oa1);
                    b1v = umin(umax(a1, oa1), umin(b1v, ob1));
                    a1 = n1;
                }
                if (r == myrk) {
                    idx0 = (int)((hi2 ? b0v : a0) & 127u);
                    idx1 = (int)((hi2 ? b1v : a1) & 127u);
                }
                pop_shift(k0, a0); pop_shift(k0, b0v);
                pop_shift(k1, a1); pop_shift(k1, b1v);
            }
            float rx0 = px[idx0] - qx0, ry0 = py[idx0] - qy0, rz0 = pz[idx0] - qz0;
            float rx1 = px[idx1] - qx1, ry1 = py[idx1] - qy1, rz1 = pz[idx1] - qz1;
            float mx0 = rx0*rx0 + ry0*ry0 + rz0*rz0;
            float mx1 = rx1*rx1 + ry1*ry1 + rz1*rz1;
            #pragma unroll
            for (int st = 1; st < 16; st <<= 1) {
                mx0 = fmaxf(mx0, __shfl_xor_sync(0xffffffffu, mx0, st, 16));
                mx1 = fmaxf(mx1, __shfl_xor_sync(0xffffffffu, mx1, st, 16));
            }
            float inv0 = 1.0f / fmaxf(sqrtf(mx0), 1e-8f);
            float inv1 = 1.0f / fmaxf(sqrtf(mx1), 1e-8f);
            srel[q0*16 + n16] = make_float4(rx0*inv0, ry0*inv0, rz0*inv0, 0.0f);
            srel[q1*16 + n16] = make_float4(rx1*inv1, ry1*inv1, rz1*inv1, 0.0f);
        }
        __syncwarp();   // warp-local: this warp's 16 points are complete
    }

    const uint2* w2p = w2H + lane;
    const uint2* w3p = w3H + lane;

    // ---- per-chunk GEMM pipeline: 8 chunks of (2 points x 16 neighbors) ----
    #pragma unroll 1
    for (int ch = 0; ch < 8; ++ch) {
        const int pA = 16*w + 2*ch;
        const int pB = pA + 1;

        uint af[2][4][4];

        // ---- layer 1+2+epi1, one m-tile at a time (c2 stays at 32 regs) ----
        #pragma unroll
        for (int mm = 0; mm < 2; ++mm) {
            const int p = mm ? pB : pA;
            float4 v0 = srel[p*16 + g];
            float4 v8 = srel[p*16 + g + 8];

            uint afr[2][4];
            #pragma unroll
            for (int blk = 0; blk < 4; ++blk) {
                const int c0 = blk*8 + 2*tg;
                const float wa0 = sW1[c0],   wb0 = sW1[32+c0],   wc0 = sW1[64+c0],   bb0 = sb1[c0];
                const float wa1 = sW1[c0+1], wb1 = sW1[32+c0+1], wc1 = sW1[64+c0+1], bb1 = sb1[c0+1];
                const int kt = blk >> 1, hi = blk & 1;
                float hg0  = fmaxf(bb0 + v0.x*wa0 + v0.y*wb0 + v0.z*wc0, 0.0f);
                float hg1  = fmaxf(bb1 + v0.x*wa1 + v0.y*wb1 + v0.z*wc1, 0.0f);
                float hg80 = fmaxf(bb0 + v8.x*wa0 + v8.y*wb0 + v8.z*wc0, 0.0f);
                float hg81 = fmaxf(bb1 + v8.x*wa1 + v8.y*wb1 + v8.z*wc1, 0.0f);
                afr[kt][hi*2+0] = packh2(hg0,  hg1);
                afr[kt][hi*2+1] = packh2(hg80, hg81);
            }

            float c2[8][4];
            #pragma unroll
            for (int nt = 0; nt < 8; ++nt)
                #pragma unroll
                for (int r = 0; r < 4; ++r) c2[nt][r] = 0.0f;
            #pragma unroll
            for (int kt = 0; kt < 2; ++kt) {
                #pragma unroll
                for (int nt = 0; nt < 8; ++nt) {
                    uint2 bq = w2p[(nt*2 + kt)*32];
                    mma16(c2[nt], afr[kt], bq.x, bq.y);
                }
            }

            #pragma unroll
            for (int kt = 0; kt < 4; ++kt) {
                const int colA = (2*kt)*8 + 2*tg;
                const int colB = (2*kt+1)*8 + 2*tg;
                const float bA0 = sb2[colA], bA1 = sb2[colA+1];
                const float bB0 = sb2[colB], bB1 = sb2[colB+1];
                af[mm][kt][0] = packh2(fmaxf(c2[2*kt][0]   + bA0, 0.0f),
                                       fmaxf(c2[2*kt][1]   + bA1, 0.0f));
                af[mm][kt][1] = packh2(fmaxf(c2[2*kt][2]   + bA0, 0.0f),
                                       fmaxf(c2[2*kt][3]   + bA1, 0.0f));
                af[mm][kt][2] = packh2(fmaxf(c2[2*kt+1][0] + bB0, 0.0f),
                                       fmaxf(c2[2*kt+1][1] + bB1, 0.0f));
                af[mm][kt][3] = packh2(fmaxf(c2[2*kt+1][2] + bB0, 0.0f),
                                       fmaxf(c2[2*kt+1][3] + bB1, 0.0f));
            }
        }

        // ---- layer 3 (B-frag shared across both m-tiles) + routed max epilogue ----
        const size_t rbA = ((size_t)(m*128 + pA)) * 128;
        const size_t rbB = ((size_t)(m*128 + pB)) * 128;
        #pragma unroll 1
        for (int pp = 0; pp < 2; ++pp) {
            #pragma unroll 1
            for (int nh = 0; nh < 2; ++nh) {
                float c3[2][4][4];
                #pragma unroll
                for (int n2 = 0; n2 < 4; ++n2)
                    #pragma unroll
                    for (int r = 0; r < 4; ++r) { c3[0][n2][r] = 0.0f; c3[1][n2][r] = 0.0f; }
                #pragma unroll
                for (int kt = 0; kt < 4; ++kt) {
                    #pragma unroll
                    for (int n2 = 0; n2 < 4; ++n2) {
                        const int ntg = pp*8 + nh*4 + n2;
                        uint2 bq = w3p[(ntg*4 + kt)*32];
                        mma16(c3[0][n2], af[0][kt], bq.x, bq.y);
                        mma16(c3[1][n2], af[1][kt], bq.x, bq.y);
                    }
                }
                #pragma unroll
                for (int mm = 0; mm < 2; ++mm) {
                    float P[4][2];
                    #pragma unroll
                    for (int n2 = 0; n2 < 4; ++n2) {
                        P[n2][0] = fmaxf(c3[mm][n2][0], c3[mm][n2][2]);
                        P[n2][1] = fmaxf(c3[mm][n2][1], c3[mm][n2][3]);
                    }
                    float e0 = g0 ? P[0][0] : P[1][0];
                    float e1 = g0 ? P[0][1] : P[1][1];
                    float e2 = g0 ? P[2][0] : P[3][0];
                    float e3 = g0 ? P[2][1] : P[3][1];
                    float K0v0 = g0 ? P[1][0] : P[0][0];
                    float K0v1 = g0 ? P[1][1] : P[0][1];
                    float K1v0 = g0 ? P[3][0] : P[2][0];
                    float K1v1 = g0 ? P[3][1] : P[2][1];
                    K0v0 = fmaxf(K0v0, __shfl_xor_sync(0xffffffffu, e0, 4));
                    K0v1 = fmaxf(K0v1, __shfl_xor_sync(0xffffffffu, e1, 4));
                    K1v0 = fmaxf(K1v0, __shfl_xor_sync(0xffffffffu, e2, 4));
                    K1v1 = fmaxf(K1v1, __shfl_xor_sync(0xffffffffu, e3, 4));
                    float f0  = g1 ? K0v0 : K1v0;
                    float f1  = g1 ? K0v1 : K1v1;
                    float Rv0 = g1 ? K1v0 : K0v0;
                    float Rv1 = g1 ? K1v1 : K0v1;
                    Rv0 = fmaxf(Rv0, __shfl_xor_sync(0xffffffffu, f0, 8));
                    Rv1 = fmaxf(Rv1, __shfl_xor_sync(0xffffffffu, f1, 8));
                    Rv0 = fmaxf(Rv0, __shfl_xor_sync(0xffffffffu, Rv0, 16));
                    Rv1 = fmaxf(Rv1, __shfl_xor_sync(0xffffffffu, Rv1, 16));
                    if (g2 == nh) {
                        const int col = (pp*8 + nh*4 + (g & 3))*8 + 2*tg;
                        float2 b3v = *(float2*)&sb3[col];
                        *(float2*)&out[(mm ? rbB : rbA) + col] =
                            make_float2(Rv0 + b3v.x, Rv1 + b3v.y);
                    }
                }
            }
        }
    }
}

extern "C" void kernel_launch(void* const* d_in, const int* in_sizes, int n_in,
                              void* d_out, int out_size)
{
    const float* windows = (const float*)d_in[0];
    const float* W1 = (const float*)d_in[1];
    const float* b1 = (const float*)d_in[2];
    const float* W2 = (const float*)d_in[3];
    const float* b2 = (const float*)d_in[4];
    const float* W3 = (const float*)d_in[5];
    const float* b3 = (const float*)d_in[6];
    float* out = (float*)d_out;

    cudaFuncSetAttribute(mini_embedding_fused,
                         cudaFuncAttributeMaxDynamicSharedMemorySize, SMEM_TOTAL);

    const int M = in_sizes[0] / (128 * 3);
    mini_embedding_fused<<<M, NT, SMEM_TOTAL>>>(windows, W1, b1, W2, b2, W3, b3, out);
}

// round 17
// speedup vs baseline: 1.2359x; 1.0117x over previous
#include <cuda_runtime.h>
#include <cuda_fp16.h>
#include <cstdint>

typedef unsigned int uint;

#define NT 256

// ---------------- dynamic smem layout (bytes) ----------------
#define OFF_W1   0        // 3*32*4 = 384
#define OFF_B1   384
#define OFF_B2   512
#define OFF_B3   768
#define OFF_PX   1280     // 4*512 = 2048 (points + sq norms)
#define OFF_W2H  3328     // uint2[8][2][32]  = 4096
#define OFF_W3H  7424     // uint2[16][4][32] = 16384
#define OFF_SREL 23808    // float4[128*16]   = 32768
#define SMEM_TOTAL 56576

__device__ __forceinline__ uint packh2(float lo, float hi) {
    __half2 h = __floats2half2_rn(lo, hi);
    return *(uint*)&h;
}
__device__ __forceinline__ void mma16(float c[4], const uint a[4], uint b0, uint b1) {
    asm volatile(
        "mma.sync.aligned.m16n8k16.row.col.f32.f16.f16.f32 "
        "{%0,%1,%2,%3}, {%4,%5,%6,%7}, {%8,%9}, {%0,%1,%2,%3};"
        : "+f"(c[0]), "+f"(c[1]), "+f"(c[2]), "+f"(c[3])
        : "r"(a[0]), "r"(a[1]), "r"(a[2]), "r"(a[3]), "r"(b0), "r"(b1));
}
__device__ __forceinline__ uint fmono(float x) {
    uint b = __float_as_uint(x);
    return b ^ (uint)((((int)b) >> 31) | 0x80000000);
}
__device__ __forceinline__ void cas(uint& a, uint& b) {
    uint lo = umin(a, b), hi = umax(a, b);
    a = lo; b = hi;
}
// Batcher 19-comparator full sort of 8 (ascending)
__device__ __forceinline__ void sort8(uint k[8]) {
    cas(k[0],k[1]); cas(k[2],k[3]); cas(k[4],k[5]); cas(k[6],k[7]);
    cas(k[0],k[2]); cas(k[1],k[3]); cas(k[4],k[6]); cas(k[5],k[7]);
    cas(k[1],k[2]); cas(k[5],k[6]); cas(k[0],k[4]); cas(k[1],k[5]);
    cas(k[2],k[6]); cas(k[3],k[7]);
    cas(k[1],k[4]); cas(k[3],k[6]);
    cas(k[2],k[4]); cas(k[3],k[5]);
    cas(k[3],k[4]);
}
// sort a BITONIC 8-sequence ascending (12 CAS: strides 4,2,1)
__device__ __forceinline__ void bsort8(uint k[8]) {
    cas(k[0],k[4]); cas(k[1],k[5]); cas(k[2],k[6]); cas(k[3],k[7]);
    cas(k[0],k[2]); cas(k[1],k[3]); cas(k[4],k[6]); cas(k[5],k[7]);
    cas(k[0],k[1]); cas(k[2],k[3]); cas(k[4],k[5]); cas(k[6],k[7]);
}

__global__ void __launch_bounds__(NT, 3)
mini_embedding_fused(const float* __restrict__ windows,
                     const float* __restrict__ W1, const float* __restrict__ b1,
                     const float* __restrict__ W2, const float* __restrict__ b2,
                     const float* __restrict__ W3, const float* __restrict__ b3,
                     float* __restrict__ out)
{
    extern __shared__ unsigned char smraw[];
    float* sW1 = (float*)(smraw + OFF_W1);
    float* sb1 = (float*)(smraw + OFF_B1);
    float* sb2 = (float*)(smraw + OFF_B2);
    float* sb3 = (float*)(smraw + OFF_B3);
    float* px  = (float*)(smraw + OFF_PX);
    float* py  = px + 128;
    float* pz  = px + 256;
    float* sqn = px + 384;
    uint2* w2H = (uint2*)(smraw + OFF_W2H);
    uint2* w3H = (uint2*)(smraw + OFF_W3H);
    float4* srel = (float4*)(smraw + OFF_SREL);

    const int tid  = threadIdx.x;
    const int w    = tid >> 5;
    const int lane = tid & 31;
    const int g    = lane >> 2;
    const int tg   = lane & 3;
    const int m    = blockIdx.x;

    const bool g0 = (lane >> 2) & 1;
    const bool g1 = (lane >> 3) & 1;
    const int  g2 = (lane >> 4) & 1;

    // ---- cooperative prep: points + weights ----
    const float* wptr = windows + (size_t)m * 128 * 3;
    for (int i = tid; i < 128; i += NT) {
        float x = wptr[i*3+0], y = wptr[i*3+1], z = wptr[i*3+2];
        px[i] = x; py[i] = y; pz[i] = z;
        sqn[i] = x*x + y*y + z*z;
    }
    for (int i = tid; i < 96;  i += NT) sW1[i] = W1[i];
    for (int i = tid; i < 32;  i += NT) sb1[i] = b1[i];
    for (int i = tid; i < 64;  i += NT) sb2[i] = b2[i];
    for (int i = tid; i < 128; i += NT) sb3[i] = b3[i];
    for (int i = tid; i < 512; i += NT) {
        int ln = i & 31, kt = (i >> 5) & 1, nt = i >> 6;
        int gg = ln >> 2, tt = ln & 3;
        int c = nt*8 + gg;
        int k0 = 16*kt + 2*tt;
        w2H[i] = make_uint2(packh2(W2[k0*64 + c],     W2[(k0+1)*64 + c]),
                            packh2(W2[(k0+8)*64 + c], W2[(k0+9)*64 + c]));
    }
    for (int i = tid; i < 2048; i += NT) {
        int ln = i & 31, kt = (i >> 5) & 3, ntg = i >> 7;
        int gg = ln >> 2, tt = ln & 3;
        int c = ntg*8 + gg;
        int k0 = 16*kt + 2*tt;
        w3H[i] = make_uint2(packh2(W3[k0*128 + c],     W3[(k0+1)*128 + c]),
                            packh2(W3[(k0+8)*128 + c], W3[(k0+9)*128 + c]));
    }
    __syncthreads();

    // ---- warp-local kNN via distributed bitonic top-16 (set-invariant) ----
    {
        const int half = lane >> 4;
        const int n16  = lane & 15;
        const int jb   = n16 * 8;
        const bool oddl = n16 & 1;
        const int sel   = n16 >> 1;

        #pragma unroll 1
        for (int i4 = 0; i4 < 4; ++i4) {
            const int q0 = 16*w + 4*i4 + 2*half;
            const int q1 = q0 + 1;
            const float qx0 = px[q0], qy0 = py[q0], qz0 = pz[q0], sq0 = sqn[q0];
            const float qx1 = px[q1], qy1 = py[q1], qz1 = pz[q1], sq1 = sqn[q1];
            uint k0[8], k1[8];
            #pragma unroll
            for (int ii = 0; ii < 8; ++ii) {
                const int j = jb + ii;
                const float xj = px[j], yj = py[j], zj = pz[j], sj = sqn[j];
                float d0 = sq0 + sj - 2.0f*(qx0*xj + qy0*yj + qz0*zj);
                float d1 = sq1 + sj - 2.0f*(qx1*xj + qy1*yj + qz1*zj);
                k0[ii] = (fmono(d0) & 0xFFFFFF80u) | (uint)j;
                k1[ii] = (fmono(d1) & 0xFFFFFF80u) | (uint)j;
            }
            sort8(k0); sort8(k1);

            // phase 1: merge lane-pairs (xor 1) -> sorted 16 across each pair
            {
                uint r0[8], r1[8];
                #pragma unroll
                for (int j = 0; j < 8; ++j) {
                    r0[j] = __shfl_xor_sync(0xffffffffu, k0[j], 1, 16);
                    r1[j] = __shfl_xor_sync(0xffffffffu, k1[j], 1, 16);
                }
                #pragma unroll
                for (int i = 0; i < 8; ++i) {
                    uint v0 = r0[7-i], v1 = r1[7-i];
                    k0[i] = oddl ? umax(k0[i], v0) : umin(k0[i], v0);
                    k1[i] = oddl ? umax(k1[i], v1) : umin(k1[i], v1);
                }
                bsort8(k0); bsort8(k1);
            }
            // phases 2..4: merge sorted-16 groups, keep smallest 16
            #pragma unroll
            for (int ph = 0; ph < 3; ++ph) {
                const int xv = (ph == 0) ? 3 : (ph == 1) ? 5 : 9;
                uint r0[8], r1[8];
                #pragma unroll
                for (int j = 0; j < 8; ++j) {
                    r0[j] = __shfl_xor_sync(0xffffffffu, k0[j], xv, 16);
                    r1[j] = __shfl_xor_sync(0xffffffffu, k1[j], xv, 16);
                }
                #pragma unroll
                for (int i = 0; i < 8; ++i) {
                    k0[i] = umin(k0[i], r0[7-i]);
                    k1[i] = umin(k1[i], r1[7-i]);
                }
                // pair re-sort: stride-8 cross (xor 1, same reg index)
                #pragma unroll
                for (int j = 0; j < 8; ++j) {
                    uint s0 = __shfl_xor_sync(0xffffffffu, k0[j], 1, 16);
                    uint s1 = __shfl_xor_sync(0xffffffffu, k1[j], 1, 16);
                    k0[j] = oddl ? umax(k0[j], s0) : umin(k0[j], s0);
                    k1[j] = oddl ? umax(k1[j], s1) : umin(k1[j], s1);
                }
                bsort8(k0); bsort8(k1);
            }
            // extract one distinct element per lane: even lanes -> ranks 0..7,
            // odd lanes -> ranks 8..15 (order irrelevant downstream)
            uint m0 = k0[0], m1 = k1[0];
            #pragma unroll
            for (int j = 1; j < 8; ++j) {
                if (sel == j) { m0 = k0[j]; m1 = k1[j]; }
            }
            const int idx0 = (int)(m0 & 127u);
            const int idx1 = (int)(m1 & 127u);

            float rx0 = px[idx0] - qx0, ry0 = py[idx0] - qy0, rz0 = pz[idx0] - qz0;
            float rx1 = px[idx1] - qx1, ry1 = py[idx1] - qy1, rz1 = pz[idx1] - qz1;
            float mx0 = rx0*rx0 + ry0*ry0 + rz0*rz0;
            float mx1 = rx1*rx1 + ry1*ry1 + rz1*rz1;
            #pragma unroll
            for (int st = 1; st < 16; st <<= 1) {
                mx0 = fmaxf(mx0, __shfl_xor_sync(0xffffffffu, mx0, st, 16));
                mx1 = fmaxf(mx1, __shfl_xor_sync(0xffffffffu, mx1, st, 16));
            }
            float inv0 = 1.0f / fmaxf(sqrtf(mx0), 1e-8f);
            float inv1 = 1.0f / fmaxf(sqrtf(mx1), 1e-8f);
            srel[q0*16 + n16] = make_float4(rx0*inv0, ry0*inv0, rz0*inv0, 0.0f);
            srel[q1*16 + n16] = make_float4(rx1*inv1, ry1*inv1, rz1*inv1, 0.0f);
        }
        __syncwarp();
    }

    const uint2* w2p = w2H + lane;
    const uint2* w3p = w3H + lane;

    // ---- per-chunk GEMM pipeline: 8 chunks of (2 points x 16 neighbors) ----
    #pragma unroll 1
    for (int ch = 0; ch < 8; ++ch) {
        const int pA = 16*w + 2*ch;
        const int pB = pA + 1;

        uint af[2][4][4];

        // ---- layer 1+2+epi1, one m-tile at a time (c2 stays at 32 regs) ----
        #pragma unroll
        for (int mm = 0; mm < 2; ++mm) {
            const int p = mm ? pB : pA;
            float4 v0 = srel[p*16 + g];
            float4 v8 = srel[p*16 + g + 8];

            uint afr[2][4];
            #pragma unroll
            for (int blk = 0; blk < 4; ++blk) {
                const int c0 = blk*8 + 2*tg;
                const float wa0 = sW1[c0],   wb0 = sW1[32+c0],   wc0 = sW1[64+c0],   bb0 = sb1[c0];
                const float wa1 = sW1[c0+1], wb1 = sW1[32+c0+1], wc1 = sW1[64+c0+1], bb1 = sb1[c0+1];
                const int kt = blk >> 1, hi = blk & 1;
                float hg0  = fmaxf(bb0 + v0.x*wa0 + v0.y*wb0 + v0.z*wc0, 0.0f);
                float hg1  = fmaxf(bb1 + v0.x*wa1 + v0.y*wb1 + v0.z*wc1, 0.0f);
                float hg80 = fmaxf(bb0 + v8.x*wa0 + v8.y*wb0 + v8.z*wc0, 0.0f);
                float hg81 = fmaxf(bb1 + v8.x*wa1 + v8.y*wb1 + v8.z*wc1, 0.0f);
                afr[kt][hi*2+0] = packh2(hg0,  hg1);
                afr[kt][hi*2+1] = packh2(hg80, hg81);
            }

            float c2[8][4];
            #pragma unroll
            for (int nt = 0; nt < 8; ++nt)
                #pragma unroll
                for (int r = 0; r < 4; ++r) c2[nt][r] = 0.0f;
            #pragma unroll
            for (int kt = 0; kt < 2; ++kt) {
                #pragma unroll
                for (int nt = 0; nt < 8; ++nt) {
                    uint2 bq = w2p[(nt*2 + kt)*32];
                    mma16(c2[nt], afr[kt], bq.x, bq.y);
                }
            }

            #pragma unroll
            for (int kt = 0; kt < 4; ++kt) {
                const int colA = (2*kt)*8 + 2*tg;
                const int colB = (2*kt+1)*8 + 2*tg;
                const float bA0 = sb2[colA], bA1 = sb2[colA+1];
                const float bB0 = sb2[colB], bB1 = sb2[colB+1];
                af[mm][kt][0] = packh2(fmaxf(c2[2*kt][0]   + bA0, 0.0f),
                                       fmaxf(c2[2*kt][1]   + bA1, 0.0f));
                af[mm][kt][1] = packh2(fmaxf(c2[2*kt][2]   + bA0, 0.0f),
                                       fmaxf(c2[2*kt][3]   + bA1, 0.0f));
                af[mm][kt][2] = packh2(fmaxf(c2[2*kt+1][0] + bB0, 0.0f),
                                       fmaxf(c2[2*kt+1][1] + bB1, 0.0f));
                af[mm][kt][3] = packh2(fmaxf(c2[2*kt+1][2] + bB0, 0.0f),
                                       fmaxf(c2[2*kt+1][3] + bB1, 0.0f));
            }
        }

        // ---- layer 3 (B-frag shared across both m-tiles) + routed max epilogue ----
        const size_t rbA = ((size_t)(m*128 + pA)) * 128;
        const size_t rbB = ((size_t)(m*128 + pB)) * 128;
        #pragma unroll 1
        for (int pp = 0; pp < 2; ++pp) {
            #pragma unroll 1
            for (int nh = 0; nh < 2; ++nh) {
                float c3[2][4][4];
                #pragma unroll
                for (int n2 = 0; n2 < 4; ++n2)
                    #pragma unroll
                    for (int r = 0; r < 4; ++r) { c3[0][n2][r] = 0.0f; c3[1][n2][r] = 0.0f; }
                #pragma unroll
                for (int kt = 0; kt < 4; ++kt) {
                    #pragma unroll
                    for (int n2 = 0; n2 < 4; ++n2) {
                        const int ntg = pp*8 + nh*4 + n2;
                        uint2 bq = w3p[(ntg*4 + kt)*32];
                        mma16(c3[0][n2], af[0][kt], bq.x, bq.y);
                        mma16(c3[1][n2], af[1][kt], bq.x, bq.y);
                    }
                }
                #pragma unroll
                for (int mm = 0; mm < 2; ++mm) {
                    float P[4][2];
                    #pragma unroll
                    for (int n2 = 0; n2 < 4; ++n2) {
                        P[n2][0] = fmaxf(c3[mm][n2][0], c3[mm][n2][2]);
                        P[n2][1] = fmaxf(c3[mm][n2][1], c3[mm][n2][3]);
                    }
                    float e0 = g0 ? P[0][0] : P[1][0];
                    float e1 = g0 ? P[0][1] : P[1][1];
                    float e2 = g0 ? P[2][0] : P[3][0];
                    float e3 = g0 ? P[2][1] : P[3][1];
                    float K0v0 = g0 ? P[1][0] : P[0][0];
                    float K0v1 = g0 ? P[1][1] : P[0][1];
                    float K1v0 = g0 ? P[3][0] : P[2][0];
                    float K1v1 = g0 ? P[3][1] : P[2][1];
                    K0v0 = fmaxf(K0v0, __shfl_xor_sync(0xffffffffu, e0, 4));
                    K0v1 = fmaxf(K0v1, __shfl_xor_sync(0xffffffffu, e1, 4));
                    K1v0 = fmaxf(K1v0, __shfl_xor_sync(0xffffffffu, e2, 4));
                    K1v1 = fmaxf(K1v1, __shfl_xor_sync(0xffffffffu, e3, 4));
                    float f0  = g1 ? K0v0 : K1v0;
                    float f1  = g1 ? K0v1 : K1v1;
                    float Rv0 = g1 ? K1v0 : K0v0;
                    float Rv1 = g1 ? K1v1 : K0v1;
                    Rv0 = fmaxf(Rv0, __shfl_xor_sync(0xffffffffu, f0, 8));
                    Rv1 = fmaxf(Rv1, __shfl_xor_sync(0xffffffffu, f1, 8));
                    Rv0 = fmaxf(Rv0, __shfl_xor_sync(0xffffffffu, Rv0, 16));
                    Rv1 = fmaxf(Rv1, __shfl_xor_sync(0xffffffffu, Rv1, 16));
                    if (g2 == nh) {
                        const int col = (pp*8 + nh*4 + (g & 3))*8 + 2*tg;
                        float2 b3v = *(float2*)&sb3[col];
                        *(float2*)&out[(mm ? rbB : rbA) + col] =
                            make_float2(Rv0 + b3v.x, Rv1 + b3v.y);
                    }
                }
            }
        }
    }
}

extern "C" void kernel_launch(void* const* d_in, const int* in_sizes, int n_in,
                              void* d_out, int out_size)
{
    const float* windows = (const float*)d_in[0];
    const float* W1 = (const float*)d_in[1];
    const float* b1 = (const float*)d_in[2];
    const float* W2 = (const float*)d_in[3];
    const float* b2 = (const float*)d_in[4];
    const float* W3 = (const float*)d_in[5];
    const float* b3 = (const float*)d_in[6];
    float* out = (float*)d_out;

    cudaFuncSetAttribute(mini_embedding_fused,
                         cudaFuncAttributeMaxDynamicSharedMemorySize, SMEM_TOTAL);

    const int M = in_sizes[0] / (128 * 3);
    mini_embedding_fused<<<M, NT, SMEM_TOTAL>>>(windows, W1, b1, W2, b2, W3, b3, out);
}